// round 4
// baseline (speedup 1.0000x reference)
#include <cuda_runtime.h>
#include <math.h>

// ---------------------------------------------------------------------------
// YOLOv1 loss — single fused kernel, d^2-inline staging (half the smem).
// pred/target: [B,14,14,90] f32, out: scalar f32.
//
// Each block iterates over groups of 64 cells:
//   A) stream 64*90 floats of pred+target via float4; class channels are
//      squared-differenced IN REGISTERS and stored once (sd); the 10 pred
//      scalars + 5 target scalars per cell go to tiny side arrays.
//   B) 64 threads compute per-cell scalar terms, compact responsible cells
//   C) 256 threads sum precomputed d^2 for responsible cells only (~5%)
// Block reduce -> global atomics -> last-block finalize (resets state so
// graph replays are deterministic).
//
// g_acc: 0 coord  1 conf  2 noobj1_num  3 n_noobj  4 sum(pc2^2)
//        5 n1     6 n2    7 cls1        8 cls2     9 nan flag
// ---------------------------------------------------------------------------

#define SGRID  14
#define NCLS   80
#define STRIDE 90
#define CELLS  64
#define GROUP_F (CELLS * STRIDE)        // 5760 floats
#define NBLOCKS 912                     // 152 SMs * 6 blocks
#define LAMBDA_COORD 5.0f
#define LAMBDA_NOOBJ 0.5f
#define EPS_IOU 1e-6f
#define EPS_WH  1e-8f

__device__ float        g_acc[10] = {0};
__device__ unsigned int g_count   = 0;

__device__ __forceinline__ float iou_img(float x1, float y1, float w1, float h1,
                                         float x2, float y2, float w2, float h2) {
    float ix0 = fmaxf(x1 - w1 * 0.5f, x2 - w2 * 0.5f);
    float iy0 = fmaxf(y1 - h1 * 0.5f, y2 - h2 * 0.5f);
    float ix1 = fminf(x1 + w1 * 0.5f, x2 + w2 * 0.5f);
    float iy1 = fminf(y1 + h1 * 0.5f, y2 + h2 * 0.5f);
    float inter = fmaxf(ix1 - ix0, 0.0f) * fmaxf(iy1 - iy0, 0.0f);
    float uni   = w1 * h1 + w2 * h2 - inter;
    return inter / (uni + EPS_IOU);
}

__global__ void __launch_bounds__(256, 6)
yolo_fused_kernel(const float* __restrict__ pred,
                  const float* __restrict__ targ,
                  float* __restrict__ out,
                  int ncells)
{
    __shared__ float sd[GROUP_F];        // d^2 for class channels (linear idx)
    __shared__ float ps[CELLS * 10];     // pred scalars per cell
    __shared__ float ts[CELLS * 5];      // target scalars per cell
    __shared__ float sm_m[CELLS];        // +1 resp1, -1 resp2, 0 none
    __shared__ int   s_list[CELLS];
    __shared__ int   s_cnt;
    __shared__ float sb[8][9];
    __shared__ unsigned int sn[8];
    __shared__ bool  is_last;

    const unsigned FULL = 0xffffffffu;
    const int tid  = threadIdx.x;
    const int lane = tid & 31;
    const int wib  = tid >> 5;
    const int ngroups = (ncells + CELLS - 1) / CELLS;

    float a[9];
#pragma unroll
    for (int i = 0; i < 9; i++) a[i] = 0.0f;
    unsigned int nanf = 0u;

    for (int g = blockIdx.x; g < ngroups; g += gridDim.x) {
        const int cbase = g * CELLS;
        const int cells = min(CELLS, ncells - cbase);
        const int nf    = cells * STRIDE;
        const int nv    = nf >> 2;

        // ---- Phase A: stream group, d^2 inline, scalars to side arrays ----
        const float4* pg = (const float4*)(pred + (size_t)cbase * STRIDE);
        const float4* tg = (const float4*)(targ + (size_t)cbase * STRIDE);
        if (tid == 0) s_cnt = 0;
#pragma unroll
        for (int k = 0; k < 6; k++) {
            int i2 = tid + k * 256;
            if (i2 < nv) {
                float4 v = pg[i2];
                float4 w = tg[i2];
                nanf |= (unsigned)((v.x != v.x) | (v.y != v.y) |
                                   (v.z != v.z) | (v.w != v.w) |
                                   (w.x != w.x) | (w.y != w.y) |
                                   (w.z != w.z) | (w.w != w.w));
                int idx  = i2 << 2;
                int cell = idx / STRIDE;
                int ch   = idx - cell * STRIDE;
                float pv0 = v.x, pv1 = v.y, pv2 = v.z, pv3 = v.w;
                float tv0 = w.x, tv1 = w.y, tv2 = w.z, tv3 = w.w;
#pragma unroll
                for (int j = 0; j < 4; j++) {
                    float pv = (j == 0) ? pv0 : (j == 1) ? pv1 : (j == 2) ? pv2 : pv3;
                    float tv = (j == 0) ? tv0 : (j == 1) ? tv1 : (j == 2) ? tv2 : tv3;
                    int chj = ch + j;
                    int cellj = cell;
                    if (chj >= STRIDE) { chj -= STRIDE; cellj++; }
                    if (chj >= 10) {
                        float d = pv - tv;
                        sd[idx + j] = d * d;
                    } else {
                        ps[cellj * 10 + chj] = pv;
                        if (chj < 5) ts[cellj * 5 + chj] = tv;
                    }
                }
            }
        }
        if (tid < (nf & 3)) {
            int i3 = (nv << 2) + tid;
            float v = (pred + (size_t)cbase * STRIDE)[i3];
            float w = (targ + (size_t)cbase * STRIDE)[i3];
            nanf |= (unsigned)((v != v) | (w != w));
            int cell = i3 / STRIDE;
            int ch   = i3 - cell * STRIDE;
            if (ch >= 10) { float d = v - w; sd[i3] = d * d; }
            else { ps[cell * 10 + ch] = v; if (ch < 5) ts[cell * 5 + ch] = w; }
        }
        __syncthreads();

        // ---- Phase B: per-cell scalars (one thread per cell) ----
        if (tid < cells) {
            const int pb = tid * 10;
            const int tb = tid * 5;
            float px1 = ps[pb + 0], py1 = ps[pb + 1];
            float pw1 = ps[pb + 2], ph1 = ps[pb + 3];
            float pc1 = ps[pb + 4];
            float px2 = ps[pb + 5], py2 = ps[pb + 6];
            float pw2 = ps[pb + 7], ph2 = ps[pb + 8];
            float pc2 = ps[pb + 9];
            float tx  = ts[tb + 0], ty = ts[tb + 1];
            float tw  = ts[tb + 2], th = ts[tb + 3];
            float tcf = ts[tb + 4];

            int gc = cbase + tid;
            float cx = (float)(gc % SGRID);
            float cy = (float)((gc / SGRID) % SGRID);

            const float invS = 1.0f / (float)SGRID;
            float X1 = (cx + px1) * invS, Y1 = (cy + py1) * invS;
            float X2 = (cx + px2) * invS, Y2 = (cy + py2) * invS;
            float TX = (cx + tx ) * invS, TY = (cy + ty ) * invS;

            float iou1 = iou_img(X1, Y1, pw1, ph1, TX, TY, tw, th);
            float iou2 = iou_img(X2, Y2, pw2, ph2, TX, TY, tw, th);

            bool obj   = (tcf == 1.0f);
            bool noobj = (tcf == 0.0f);

            a[4] += pc2 * pc2;
            if (noobj) { a[2] += pc1 * pc1; a[3] += 1.0f; }

            float m = 0.0f;
            if (obj) {
                bool r1 = (iou1 >= iou2);
                m = r1 ? 1.0f : -1.0f;
                float sw1 = sqrtf(fmaxf(pw1, EPS_WH)) - sqrtf(fmaxf(tw, EPS_WH));
                float sh1 = sqrtf(fmaxf(ph1, EPS_WH)) - sqrtf(fmaxf(th, EPS_WH));
                float sw2 = sqrtf(fmaxf(pw2, EPS_WH)) - sqrtf(fmaxf(tw, EPS_WH));
                float sh2 = sqrtf(fmaxf(ph2, EPS_WH)) - sqrtf(fmaxf(th, EPS_WH));
                float c1 = (px1 - tx) * (px1 - tx) + (py1 - ty) * (py1 - ty)
                         + sw1 * sw1 + sh1 * sh1;
                float c2 = (px2 - tx) * (px2 - tx) + (py2 - ty) * (py2 - ty)
                         + sw2 * sw2 + sh2 * sh2;
                float e1 = pc1 - iou1;
                float e2 = pc2 - iou2;
                if (r1) {
                    a[0] += c1;
                    a[1] += e1 * e1 + pc2 * pc2;
                    a[5] += 1.0f;
                } else {
                    a[0] += c2;
                    a[1] += e2 * e2 + pc1 * pc1;
                    a[6] += 1.0f;
                }
                int pos = atomicAdd(&s_cnt, 1);
                s_list[pos] = tid;
            }
            sm_m[tid] = m;
        }
        __syncthreads();

        // ---- Phase C: sum precomputed d^2 for responsible cells ----
        const int tot = s_cnt * NCLS;
        for (int e = tid; e < tot; e += 256) {
            int k = e / NCLS;
            int j = e - k * NCLS;
            int i = s_list[k];
            float dd = sd[i * STRIDE + 10 + j];
            if (sm_m[i] > 0.0f) a[7] += dd; else a[8] += dd;
        }
        __syncthreads();
    }

    // ---- warp reduction ----
#pragma unroll
    for (int i = 0; i < 9; i++) {
        float v = a[i];
#pragma unroll
        for (int o = 16; o > 0; o >>= 1) v += __shfl_down_sync(FULL, v, o);
        a[i] = v;
    }
    unsigned int nanw = __any_sync(FULL, nanf != 0u) ? 1u : 0u;

    // ---- block reduction -> global atomics ----
    if (lane == 0) {
#pragma unroll
        for (int i = 0; i < 9; i++) sb[wib][i] = a[i];
        sn[wib] = nanw;
    }
    __syncthreads();
    if (tid < 9) {
        float v = 0.0f;
#pragma unroll
        for (int w = 0; w < 8; w++) v += sb[w][tid];
        atomicAdd(&g_acc[tid], v);
    }
    if (tid == 9) {
        unsigned int v = 0u;
#pragma unroll
        for (int w = 0; w < 8; w++) v |= sn[w];
        if (v) atomicAdd(&g_acc[9], 1.0f);
    }

    // ---- last-block finalize ----
    __threadfence();
    __syncthreads();
    if (tid == 0) {
        unsigned int old = atomicAdd(&g_count, 1u);
        is_last = (old == (unsigned int)(gridDim.x - 1));
    }
    __syncthreads();
    if (is_last && tid == 0) {
        __threadfence();
        volatile float* ga = g_acc;
        float coord   = LAMBDA_COORD * ga[0];
        float conf    = ga[1];
        float n_noobj = ga[3];
        float noobj1  = ga[2] / fmaxf(n_noobj, 1.0f);
        float noobj2  = ga[4] / (float)ncells;
        if (n_noobj > 0.0f) conf += LAMBDA_NOOBJ * (noobj1 + noobj2);
        float n1 = ga[5], n2 = ga[6];
        float cls_loss = 0.0f;
        if (n1 > 0.0f) cls_loss += ga[7] / fmaxf(n1 * (float)NCLS, 1.0f);
        if (n2 > 0.0f) cls_loss += ga[8] / fmaxf(n2 * (float)NCLS, 1.0f);
        float B = (float)ncells / (float)(SGRID * SGRID);
        float total = (coord + conf + cls_loss) / B;
        out[0] = (ga[9] != 0.0f) ? 0.0f : total;

#pragma unroll
        for (int i = 0; i < 10; i++) g_acc[i] = 0.0f;
        g_count = 0u;
    }
}

extern "C" void kernel_launch(void* const* d_in, const int* in_sizes, int n_in,
                              void* d_out, int out_size) {
    const float* pred = (const float*)d_in[0];
    const float* targ = (const float*)d_in[1];
    float* out = (float*)d_out;

    int total_elems = in_sizes[0];
    int ncells = total_elems / STRIDE;

    yolo_fused_kernel<<<NBLOCKS, 256>>>(pred, targ, out, ncells);
}

// round 5
// speedup vs baseline: 4.0449x; 4.0449x over previous
#include <cuda_runtime.h>
#include <math.h>

// ---------------------------------------------------------------------------
// YOLOv1 loss — single fused kernel, single-buffer d^2 staging.
// pred/target: [B,14,14,90] f32, out: scalar f32.
//
// Each block iterates over groups of 64 cells:
//   A) stream 64*90 float pairs via float4; store sd[i]=(p[i]-t[i])^2
//      linearly into smem (branch-free, coalesced, loads batchable).
//      NaN-checked inline.
//   B) 64 threads re-read the 15 per-cell scalars from global (L1-hot),
//      compute IoU/coord/conf terms, compact responsible cells.
//   C) 256 threads sum precomputed d^2 over class channels of responsible
//      cells only (~5%).
// Block reduce -> global atomics -> last-block finalize (resets state so
// graph replays are deterministic).
//
// g_acc: 0 coord  1 conf  2 noobj1_num  3 n_noobj  4 sum(pc2^2)
//        5 n1     6 n2    7 cls1        8 cls2     9 nan flag
// ---------------------------------------------------------------------------

#define SGRID  14
#define NCLS   80
#define STRIDE 90
#define CELLS  64
#define GROUP_F (CELLS * STRIDE)        // 5760 floats
#define NBLOCKS 912                     // 152 SMs * 6 blocks
#define LAMBDA_COORD 5.0f
#define LAMBDA_NOOBJ 0.5f
#define EPS_IOU 1e-6f
#define EPS_WH  1e-8f

__device__ float        g_acc[10] = {0};
__device__ unsigned int g_count   = 0;

__device__ __forceinline__ float iou_img(float x1, float y1, float w1, float h1,
                                         float x2, float y2, float w2, float h2) {
    float ix0 = fmaxf(x1 - w1 * 0.5f, x2 - w2 * 0.5f);
    float iy0 = fmaxf(y1 - h1 * 0.5f, y2 - h2 * 0.5f);
    float ix1 = fminf(x1 + w1 * 0.5f, x2 + w2 * 0.5f);
    float iy1 = fminf(y1 + h1 * 0.5f, y2 + h2 * 0.5f);
    float inter = fmaxf(ix1 - ix0, 0.0f) * fmaxf(iy1 - iy0, 0.0f);
    float uni   = w1 * h1 + w2 * h2 - inter;
    return inter / (uni + EPS_IOU);
}

__global__ void __launch_bounds__(256, 6)
yolo_fused_kernel(const float* __restrict__ pred,
                  const float* __restrict__ targ,
                  float* __restrict__ out,
                  int ncells)
{
    __shared__ float sd[GROUP_F];        // (p-t)^2 for every channel, linear
    __shared__ float sm_m[CELLS];        // +1 resp1, -1 resp2, 0 none
    __shared__ int   s_list[CELLS];
    __shared__ int   s_cnt;
    __shared__ float sb[8][9];
    __shared__ unsigned int sn[8];
    __shared__ bool  is_last;

    const unsigned FULL = 0xffffffffu;
    const int tid  = threadIdx.x;
    const int lane = tid & 31;
    const int wib  = tid >> 5;
    const int ngroups = (ncells + CELLS - 1) / CELLS;

    float a[9];
#pragma unroll
    for (int i = 0; i < 9; i++) a[i] = 0.0f;
    unsigned int nanf = 0u;

    for (int g = blockIdx.x; g < ngroups; g += gridDim.x) {
        const int cbase = g * CELLS;
        const int cells = min(CELLS, ncells - cbase);
        const int nf    = cells * STRIDE;
        const int nv    = nf >> 2;

        // ---- Phase A: stream group, store (p-t)^2 linearly ----
        const float4* pg = (const float4*)(pred + (size_t)cbase * STRIDE);
        const float4* tg = (const float4*)(targ + (size_t)cbase * STRIDE);
        if (tid == 0) s_cnt = 0;
#pragma unroll
        for (int k = 0; k < 6; k++) {
            int i2 = tid + k * 256;
            if (i2 < nv) {
                float4 v = pg[i2];
                float4 w = tg[i2];
                nanf |= (unsigned)((v.x != v.x) | (v.y != v.y) |
                                   (v.z != v.z) | (v.w != v.w) |
                                   (w.x != w.x) | (w.y != w.y) |
                                   (w.z != w.z) | (w.w != w.w));
                float4 d;
                d.x = (v.x - w.x) * (v.x - w.x);
                d.y = (v.y - w.y) * (v.y - w.y);
                d.z = (v.z - w.z) * (v.z - w.z);
                d.w = (v.w - w.w) * (v.w - w.w);
                ((float4*)sd)[i2] = d;
            }
        }
        if (tid < (nf & 3)) {
            int i3 = (nv << 2) + tid;
            float v = (pred + (size_t)cbase * STRIDE)[i3];
            float w = (targ + (size_t)cbase * STRIDE)[i3];
            nanf |= (unsigned)((v != v) | (w != w));
            sd[i3] = (v - w) * (v - w);
        }
        __syncthreads();

        // ---- Phase B: per-cell scalars, re-read from global (L1-hot) ----
        if (tid < cells) {
            const float* p = pred + (size_t)(cbase + tid) * STRIDE;
            const float* t = targ + (size_t)(cbase + tid) * STRIDE;
            float px1 = p[0], py1 = p[1], pw1 = p[2], ph1 = p[3], pc1 = p[4];
            float px2 = p[5], py2 = p[6], pw2 = p[7], ph2 = p[8], pc2 = p[9];
            float tx  = t[0], ty  = t[1], tw  = t[2], th  = t[3], tcf = t[4];

            int gc = cbase + tid;
            float cx = (float)(gc % SGRID);
            float cy = (float)((gc / SGRID) % SGRID);

            const float invS = 1.0f / (float)SGRID;
            float X1 = (cx + px1) * invS, Y1 = (cy + py1) * invS;
            float X2 = (cx + px2) * invS, Y2 = (cy + py2) * invS;
            float TX = (cx + tx ) * invS, TY = (cy + ty ) * invS;

            float iou1 = iou_img(X1, Y1, pw1, ph1, TX, TY, tw, th);
            float iou2 = iou_img(X2, Y2, pw2, ph2, TX, TY, tw, th);

            bool obj   = (tcf == 1.0f);
            bool noobj = (tcf == 0.0f);

            a[4] += pc2 * pc2;
            if (noobj) { a[2] += pc1 * pc1; a[3] += 1.0f; }

            float m = 0.0f;
            if (obj) {
                bool r1 = (iou1 >= iou2);
                m = r1 ? 1.0f : -1.0f;
                float sw1 = sqrtf(fmaxf(pw1, EPS_WH)) - sqrtf(fmaxf(tw, EPS_WH));
                float sh1 = sqrtf(fmaxf(ph1, EPS_WH)) - sqrtf(fmaxf(th, EPS_WH));
                float sw2 = sqrtf(fmaxf(pw2, EPS_WH)) - sqrtf(fmaxf(tw, EPS_WH));
                float sh2 = sqrtf(fmaxf(ph2, EPS_WH)) - sqrtf(fmaxf(th, EPS_WH));
                float c1 = (px1 - tx) * (px1 - tx) + (py1 - ty) * (py1 - ty)
                         + sw1 * sw1 + sh1 * sh1;
                float c2 = (px2 - tx) * (px2 - tx) + (py2 - ty) * (py2 - ty)
                         + sw2 * sw2 + sh2 * sh2;
                float e1 = pc1 - iou1;
                float e2 = pc2 - iou2;
                if (r1) {
                    a[0] += c1;
                    a[1] += e1 * e1 + pc2 * pc2;
                    a[5] += 1.0f;
                } else {
                    a[0] += c2;
                    a[1] += e2 * e2 + pc1 * pc1;
                    a[6] += 1.0f;
                }
                int pos = atomicAdd(&s_cnt, 1);
                s_list[pos] = tid;
            }
            sm_m[tid] = m;
        }
        __syncthreads();

        // ---- Phase C: sum precomputed d^2 for responsible cells ----
        const int tot = s_cnt * NCLS;
        for (int e = tid; e < tot; e += 256) {
            int k = e / NCLS;
            int j = e - k * NCLS;
            int i = s_list[k];
            float dd = sd[i * STRIDE + 10 + j];
            if (sm_m[i] > 0.0f) a[7] += dd; else a[8] += dd;
        }
        __syncthreads();
    }

    // ---- warp reduction ----
#pragma unroll
    for (int i = 0; i < 9; i++) {
        float v = a[i];
#pragma unroll
        for (int o = 16; o > 0; o >>= 1) v += __shfl_down_sync(FULL, v, o);
        a[i] = v;
    }
    unsigned int nanw = __any_sync(FULL, nanf != 0u) ? 1u : 0u;

    // ---- block reduction -> global atomics ----
    if (lane == 0) {
#pragma unroll
        for (int i = 0; i < 9; i++) sb[wib][i] = a[i];
        sn[wib] = nanw;
    }
    __syncthreads();
    if (tid < 9) {
        float v = 0.0f;
#pragma unroll
        for (int w = 0; w < 8; w++) v += sb[w][tid];
        atomicAdd(&g_acc[tid], v);
    }
    if (tid == 9) {
        unsigned int v = 0u;
#pragma unroll
        for (int w = 0; w < 8; w++) v |= sn[w];
        if (v) atomicAdd(&g_acc[9], 1.0f);
    }

    // ---- last-block finalize ----
    __threadfence();
    __syncthreads();
    if (tid == 0) {
        unsigned int old = atomicAdd(&g_count, 1u);
        is_last = (old == (unsigned int)(gridDim.x - 1));
    }
    __syncthreads();
    if (is_last && tid == 0) {
        __threadfence();
        volatile float* ga = g_acc;
        float coord   = LAMBDA_COORD * ga[0];
        float conf    = ga[1];
        float n_noobj = ga[3];
        float noobj1  = ga[2] / fmaxf(n_noobj, 1.0f);
        float noobj2  = ga[4] / (float)ncells;
        if (n_noobj > 0.0f) conf += LAMBDA_NOOBJ * (noobj1 + noobj2);
        float n1 = ga[5], n2 = ga[6];
        float cls_loss = 0.0f;
        if (n1 > 0.0f) cls_loss += ga[7] / fmaxf(n1 * (float)NCLS, 1.0f);
        if (n2 > 0.0f) cls_loss += ga[8] / fmaxf(n2 * (float)NCLS, 1.0f);
        float B = (float)ncells / (float)(SGRID * SGRID);
        float total = (coord + conf + cls_loss) / B;
        out[0] = (ga[9] != 0.0f) ? 0.0f : total;

#pragma unroll
        for (int i = 0; i < 10; i++) g_acc[i] = 0.0f;
        g_count = 0u;
    }
}

extern "C" void kernel_launch(void* const* d_in, const int* in_sizes, int n_in,
                              void* d_out, int out_size) {
    const float* pred = (const float*)d_in[0];
    const float* targ = (const float*)d_in[1];
    float* out = (float*)d_out;

    int total_elems = in_sizes[0];
    int ncells = total_elems / STRIDE;

    yolo_fused_kernel<<<NBLOCKS, 256>>>(pred, targ, out, ncells);
}